// round 1
// baseline (speedup 1.0000x reference)
#include <cuda_runtime.h>

#define HIDDEN 1024
#define NHEADS 16
#define HDIM 64
#define BATCH 2
#define SEQ 2048
#define MTOT (BATCH*SEQ)
#define SPAD 68

// context scratch, [b, s, h*64+d] layout so the out-projection reads rows contiguously
__device__ float g_ctx[(size_t)MTOT * HIDDEN];

// ---------------------------------------------------------------------------
// GEMM 1: qkv = x @ W_qkv + b_qkv, scattered into q/k/v output regions
// x: [4096, 1024], W: [1024, 3072]. Tile 64x64x16, 256 threads, 4x4/thread.
// ---------------------------------------------------------------------------
__global__ __launch_bounds__(256) void gemm_qkv_kernel(
    const float* __restrict__ A, const float* __restrict__ W,
    const float* __restrict__ bias,
    float* __restrict__ qo, float* __restrict__ ko, float* __restrict__ vo)
{
    const int K = HIDDEN, N = 3 * HIDDEN;
    __shared__ float As[16][SPAD];
    __shared__ float Bs[16][SPAD];
    int tid = threadIdx.x;
    int bm = blockIdx.y * 64, bn = blockIdx.x * 64;
    int tx = tid & 15, ty = tid >> 4;
    int arow = tid >> 2, acol = (tid & 3) << 2;
    int brow = tid >> 4, bcol = (tid & 15) << 2;
    const float* Aptr = A + (size_t)(bm + arow) * K + acol;
    const float* Wptr = W + (size_t)brow * N + bn + bcol;
    float acc[4][4] = {};
    for (int k0 = 0; k0 < K; k0 += 16) {
        float4 av = *(const float4*)(Aptr + k0);
        As[acol + 0][arow] = av.x; As[acol + 1][arow] = av.y;
        As[acol + 2][arow] = av.z; As[acol + 3][arow] = av.w;
        *(float4*)&Bs[brow][bcol] = *(const float4*)(Wptr + (size_t)k0 * N);
        __syncthreads();
#pragma unroll
        for (int kk = 0; kk < 16; kk++) {
            float4 a4 = *(float4*)&As[kk][ty << 2];
            float4 b4 = *(float4*)&Bs[kk][tx << 2];
            float a[4] = {a4.x, a4.y, a4.z, a4.w};
            float b[4] = {b4.x, b4.y, b4.z, b4.w};
#pragma unroll
            for (int i = 0; i < 4; i++)
#pragma unroll
                for (int j = 0; j < 4; j++) acc[i][j] += a[i] * b[j];
        }
        __syncthreads();
    }
#pragma unroll
    for (int i = 0; i < 4; i++) {
        int m = bm + (ty << 2) + i;
        int bb = m >> 11, s = m & (SEQ - 1);
#pragma unroll
        for (int j = 0; j < 4; j++) {
            int n = bn + (tx << 2) + j;
            float val = acc[i][j] + bias[n];
            int t = n >> 10, h = (n & 1023) >> 6, dc = n & 63;
            float* dst = (t == 0) ? qo : (t == 1 ? ko : vo);
            dst[((size_t)(bb * NHEADS + h) * SEQ + s) * HDIM + dc] = val;
        }
    }
}

// ---------------------------------------------------------------------------
// GEMM 2 (runs last): output = ctx @ W_out + b_out
// ---------------------------------------------------------------------------
__global__ __launch_bounds__(256) void gemm_out_kernel(
    const float* __restrict__ W, const float* __restrict__ bias,
    float* __restrict__ C)
{
    const int K = HIDDEN, N = HIDDEN;
    const float* A = g_ctx;
    __shared__ float As[16][SPAD];
    __shared__ float Bs[16][SPAD];
    int tid = threadIdx.x;
    int bm = blockIdx.y * 64, bn = blockIdx.x * 64;
    int tx = tid & 15, ty = tid >> 4;
    int arow = tid >> 2, acol = (tid & 3) << 2;
    int brow = tid >> 4, bcol = (tid & 15) << 2;
    const float* Aptr = A + (size_t)(bm + arow) * K + acol;
    const float* Wptr = W + (size_t)brow * N + bn + bcol;
    float acc[4][4] = {};
    for (int k0 = 0; k0 < K; k0 += 16) {
        float4 av = *(const float4*)(Aptr + k0);
        As[acol + 0][arow] = av.x; As[acol + 1][arow] = av.y;
        As[acol + 2][arow] = av.z; As[acol + 3][arow] = av.w;
        *(float4*)&Bs[brow][bcol] = *(const float4*)(Wptr + (size_t)k0 * N);
        __syncthreads();
#pragma unroll
        for (int kk = 0; kk < 16; kk++) {
            float4 a4 = *(float4*)&As[kk][ty << 2];
            float4 b4 = *(float4*)&Bs[kk][tx << 2];
            float a[4] = {a4.x, a4.y, a4.z, a4.w};
            float b[4] = {b4.x, b4.y, b4.z, b4.w};
#pragma unroll
            for (int i = 0; i < 4; i++)
#pragma unroll
                for (int j = 0; j < 4; j++) acc[i][j] += a[i] * b[j];
        }
        __syncthreads();
    }
#pragma unroll
    for (int i = 0; i < 4; i++) {
        int m = bm + (ty << 2) + i;
#pragma unroll
        for (int j = 0; j < 4; j++) {
            int n = bn + (tx << 2) + j;
            C[(size_t)m * N + n] = acc[i][j] + bias[n];
        }
    }
}

// ---------------------------------------------------------------------------
// Flash attention: one block per (q-tile of 64 rows, head, batch).
// Q/K/V read from the q/k/v output regions ([B,h,S,64] fp32).
// Online softmax, causal + padding mask, context -> g_ctx [B,S,H].
// ---------------------------------------------------------------------------
#define ATTN_SMEM_FLOATS (3 * 64 * SPAD + 64)

__global__ __launch_bounds__(256) void attn_kernel(
    const float* __restrict__ Q, const float* __restrict__ Kg,
    const float* __restrict__ Vg, const int* __restrict__ mask)
{
    extern __shared__ float sm[];
    float* Qs = sm;                 // 64 x SPAD
    float* Ks = Qs + 64 * SPAD;     // 64 x SPAD (reused for P)
    float* Vs = Ks + 64 * SPAD;     // 64 x SPAD
    float* mbias = Vs + 64 * SPAD;  // 64

    int tid = threadIdx.x;
    int qt = blockIdx.x, h = blockIdx.y, b = blockIdx.z;
    int bh = b * NHEADS + h;
    int qbase = qt * 64;
    const float* Qp = Q + ((size_t)bh * SEQ + qbase) * HDIM;
    const float* Kp = Kg + (size_t)bh * SEQ * HDIM;
    const float* Vp = Vg + (size_t)bh * SEQ * HDIM;

    // stage Q tile
    for (int i = tid; i < 1024; i += 256) {
        float4 v = ((const float4*)Qp)[i];
        int r = i >> 4, c = (i & 15) << 2;
        *(float4*)&Qs[r * SPAD + c] = v;
    }

    int tx = tid & 15, ty = tid >> 4;
    float o[4][4] = {};
    float mrow[4] = {-1e30f, -1e30f, -1e30f, -1e30f};
    float lrow[4] = {};
    const float scale = 0.125f;  // 1/sqrt(64)

    for (int kt = 0; kt <= qt; kt++) {
        int kbase = kt * 64;
        __syncthreads();  // protect Ks(P)/Vs from previous iteration's readers
        const float4* kg4 = (const float4*)(Kp + (size_t)kbase * HDIM);
        const float4* vg4 = (const float4*)(Vp + (size_t)kbase * HDIM);
        for (int i = tid; i < 1024; i += 256) {
            int r = i >> 4, c = (i & 15) << 2;
            *(float4*)&Ks[r * SPAD + c] = kg4[i];
            *(float4*)&Vs[r * SPAD + c] = vg4[i];
        }
        if (tid < 64)
            mbias[tid] = (mask[b * SEQ + kbase + tid] == 0) ? -1e30f : 0.0f;
        __syncthreads();

        // S = Q @ K^T (64x64x64), 4x4 per thread
        float sv[4][4] = {};
#pragma unroll 4
        for (int d = 0; d < 64; d += 4) {
            float4 a[4], kk[4];
#pragma unroll
            for (int i = 0; i < 4; i++) a[i] = *(float4*)&Qs[((ty << 2) + i) * SPAD + d];
#pragma unroll
            for (int j = 0; j < 4; j++) kk[j] = *(float4*)&Ks[((tx << 2) + j) * SPAD + d];
#pragma unroll
            for (int i = 0; i < 4; i++)
#pragma unroll
                for (int j = 0; j < 4; j++)
                    sv[i][j] += a[i].x * kk[j].x + a[i].y * kk[j].y +
                                a[i].z * kk[j].z + a[i].w * kk[j].w;
        }

        bool diag = (kt == qt);
#pragma unroll
        for (int i = 0; i < 4; i++) {
            int qpos = (ty << 2) + i;
#pragma unroll
            for (int j = 0; j < 4; j++) {
                int kpos = (tx << 2) + j;
                float s = sv[i][j] * scale + mbias[kpos];
                if (diag && kpos > qpos) s = -1e30f;
                sv[i][j] = s;
            }
        }

        // online softmax (row reductions across the 16 tx lanes)
#pragma unroll
        for (int i = 0; i < 4; i++) {
            float mx = fmaxf(fmaxf(sv[i][0], sv[i][1]), fmaxf(sv[i][2], sv[i][3]));
#pragma unroll
            for (int off = 8; off >= 1; off >>= 1)
                mx = fmaxf(mx, __shfl_xor_sync(0xffffffffu, mx, off, 16));
            float mnew = fmaxf(mrow[i], mx);
            float fac = __expf(mrow[i] - mnew);
            mrow[i] = mnew;
            float rs = 0.f;
#pragma unroll
            for (int j = 0; j < 4; j++) {
                float p = __expf(sv[i][j] - mnew);
                sv[i][j] = p;
                rs += p;
            }
#pragma unroll
            for (int off = 8; off >= 1; off >>= 1)
                rs += __shfl_xor_sync(0xffffffffu, rs, off, 16);
            lrow[i] = lrow[i] * fac + rs;
#pragma unroll
            for (int j = 0; j < 4; j++) o[i][j] *= fac;
        }

        // write P into Ks buffer (all S-reads of Ks are done)
        __syncthreads();
#pragma unroll
        for (int i = 0; i < 4; i++)
            *(float4*)&Ks[((ty << 2) + i) * SPAD + (tx << 2)] =
                make_float4(sv[i][0], sv[i][1], sv[i][2], sv[i][3]);
        __syncthreads();

        // O += P @ V (64x64x64)
#pragma unroll 4
        for (int t = 0; t < 64; t += 4) {
            float pm[4][4], vrm[4][4];
#pragma unroll
            for (int i = 0; i < 4; i++) {
                float4 p4 = *(float4*)&Ks[((ty << 2) + i) * SPAD + t];
                pm[i][0] = p4.x; pm[i][1] = p4.y; pm[i][2] = p4.z; pm[i][3] = p4.w;
            }
#pragma unroll
            for (int c = 0; c < 4; c++) {
                float4 v4 = *(float4*)&Vs[(t + c) * SPAD + (tx << 2)];
                vrm[c][0] = v4.x; vrm[c][1] = v4.y; vrm[c][2] = v4.z; vrm[c][3] = v4.w;
            }
#pragma unroll
            for (int i = 0; i < 4; i++)
#pragma unroll
                for (int j = 0; j < 4; j++)
                    o[i][j] += pm[i][0] * vrm[0][j] + pm[i][1] * vrm[1][j] +
                               pm[i][2] * vrm[2][j] + pm[i][3] * vrm[3][j];
        }
    }

    // normalize and write context tile
#pragma unroll
    for (int i = 0; i < 4; i++) {
        float inv = 1.0f / lrow[i];
        int srow = qbase + (ty << 2) + i;
        float4 w = make_float4(o[i][0] * inv, o[i][1] * inv, o[i][2] * inv, o[i][3] * inv);
        *(float4*)&g_ctx[(size_t)(b * SEQ + srow) * HIDDEN + h * HDIM + (tx << 2)] = w;
    }
}

// ---------------------------------------------------------------------------
extern "C" void kernel_launch(void* const* d_in, const int* in_sizes, int n_in,
                              void* d_out, int out_size) {
    const float* x    = (const float*)d_in[0];
    const int*   mask = (const int*)d_in[1];
    const float* Wqkv = (const float*)d_in[2];
    const float* bqkv = (const float*)d_in[3];
    const float* Wout = (const float*)d_in[4];
    const float* bout = (const float*)d_in[5];

    float* out = (float*)d_out;                     // [B,S,H]
    float* qo = out + (size_t)MTOT * HIDDEN;        // [B,h,S,d]
    float* ko = qo + (size_t)MTOT * HIDDEN;
    float* vo = ko + (size_t)MTOT * HIDDEN;

    const int attn_smem = ATTN_SMEM_FLOATS * (int)sizeof(float);  // 52480 B
    cudaFuncSetAttribute(attn_kernel,
                         cudaFuncAttributeMaxDynamicSharedMemorySize, attn_smem);

    gemm_qkv_kernel<<<dim3(48, 64), 256>>>(x, Wqkv, bqkv, qo, ko, vo);
    attn_kernel<<<dim3(SEQ / 64, NHEADS, BATCH), 256, attn_smem>>>(qo, ko, vo, mask);
    gemm_out_kernel<<<dim3(16, 64), 256>>>(Wout, bout, out);
}

// round 3
// speedup vs baseline: 1.4097x; 1.4097x over previous
#include <cuda_runtime.h>

#define HIDDEN 1024
#define NHEADS 16
#define HDIM 64
#define BATCH 2
#define SEQ 2048
#define MTOT (BATCH*SEQ)

typedef unsigned long long ull;

// ---- packed fp32x2 helpers (sm_100+) --------------------------------------
__device__ __forceinline__ ull dup2(float x) {
    ull r; asm("mov.b64 %0, {%1, %1};" : "=l"(r) : "f"(x)); return r;
}
__device__ __forceinline__ ull pack2(float lo, float hi) {
    ull r; asm("mov.b64 %0, {%1, %2};" : "=l"(r) : "f"(lo), "f"(hi)); return r;
}
__device__ __forceinline__ void unpack2(ull v, float& lo, float& hi) {
    asm("mov.b64 {%0, %1}, %2;" : "=f"(lo), "=f"(hi) : "l"(v));
}
__device__ __forceinline__ void fma2(ull& d, ull a, ull b) {
    asm("fma.rn.f32x2 %0, %1, %2, %0;" : "+l"(d) : "l"(a), "l"(b));
}
__device__ __forceinline__ ull mul2(ull a, ull b) {
    ull d; asm("mul.rn.f32x2 %0, %1, %2;" : "=l"(d) : "l"(a), "l"(b)); return d;
}

// context scratch, [b, s, h*64+d]
__device__ float g_ctx[(size_t)MTOT * HIDDEN];

// ---------------------------------------------------------------------------
// Shared GEMM mainloop: 128x128 tile, 256 threads, 8x8/thread, K-step 8,
// double-buffered smem, FFMA2 inner loop. K fixed = 1024.
// ---------------------------------------------------------------------------
__device__ __forceinline__ void gemm_main(
    const float* __restrict__ A, const float* __restrict__ W, int N,
    int bm, int bn, int tid,
    float As[2][8][132], float Bs[2][8][132], ull acc[8][4])
{
    const int K = HIDDEN;
    const int tx = tid & 15, ty = tid >> 4;
    const int arow = tid >> 1, acol = (tid & 1) << 2;
    const int brow = tid >> 5, bcol = (tid & 31) << 2;
    const float* Ap = A + (size_t)(bm + arow) * K + acol;
    const float* Wp = W + (size_t)brow * N + bn + bcol;

    float4 aR = *(const float4*)Ap;
    float4 bR = *(const float4*)Wp;
    As[0][acol + 0][arow] = aR.x; As[0][acol + 1][arow] = aR.y;
    As[0][acol + 2][arow] = aR.z; As[0][acol + 3][arow] = aR.w;
    *(float4*)&Bs[0][brow][bcol] = bR;
    __syncthreads();

    const int KB = K / 8;
    for (int kb = 0; kb < KB; kb++) {
        int cur = kb & 1;
        if (kb + 1 < KB) {
            aR = *(const float4*)(Ap + (size_t)(kb + 1) * 8);
            bR = *(const float4*)(Wp + (size_t)(kb + 1) * 8 * N);
        }
#pragma unroll
        for (int kk = 0; kk < 8; kk++) {
            float a[8];
            *(float4*)&a[0] = *(const float4*)&As[cur][kk][ty * 8];
            *(float4*)&a[4] = *(const float4*)&As[cur][kk][ty * 8 + 4];
            ulonglong2 b0 = *(const ulonglong2*)&Bs[cur][kk][tx * 8];
            ulonglong2 b1 = *(const ulonglong2*)&Bs[cur][kk][tx * 8 + 4];
#pragma unroll
            for (int i = 0; i < 8; i++) {
                ull ad = dup2(a[i]);
                fma2(acc[i][0], ad, b0.x);
                fma2(acc[i][1], ad, b0.y);
                fma2(acc[i][2], ad, b1.x);
                fma2(acc[i][3], ad, b1.y);
            }
        }
        if (kb + 1 < KB) {
            int nxt = cur ^ 1;
            As[nxt][acol + 0][arow] = aR.x; As[nxt][acol + 1][arow] = aR.y;
            As[nxt][acol + 2][arow] = aR.z; As[nxt][acol + 3][arow] = aR.w;
            *(float4*)&Bs[nxt][brow][bcol] = bR;
        }
        __syncthreads();
    }
}

// ---------------------------------------------------------------------------
// GEMM 1: qkv = x @ W_qkv + b_qkv  -> scatter into q/k/v [B,h,S,d] regions
// ---------------------------------------------------------------------------
__global__ __launch_bounds__(256, 2) void gemm_qkv_kernel(
    const float* __restrict__ A, const float* __restrict__ W,
    const float* __restrict__ bias,
    float* __restrict__ qo, float* __restrict__ ko, float* __restrict__ vo)
{
    __shared__ float As[2][8][132];
    __shared__ float Bs[2][8][132];
    const int N = 3 * HIDDEN;
    int tid = threadIdx.x;
    int bm = blockIdx.y * 128, bn = blockIdx.x * 128;
    ull acc[8][4] = {};
    gemm_main(A, W, N, bm, bn, tid, As, Bs, acc);

    const int tx = tid & 15, ty = tid >> 4;
    int n0 = bn + tx * 8;
    float bb8[8];
    *(float4*)&bb8[0] = *(const float4*)&bias[n0];
    *(float4*)&bb8[4] = *(const float4*)&bias[n0 + 4];
    int t = n0 >> 10, hh = (n0 & 1023) >> 6, dc = n0 & 63;
    float* base = (t == 0) ? qo : (t == 1 ? ko : vo);
#pragma unroll
    for (int i = 0; i < 8; i++) {
        int m = bm + ty * 8 + i;
        int bb = m >> 11, s = m & (SEQ - 1);
        float r[8];
#pragma unroll
        for (int jp = 0; jp < 4; jp++) unpack2(acc[i][jp], r[2 * jp], r[2 * jp + 1]);
#pragma unroll
        for (int c = 0; c < 8; c++) r[c] += bb8[c];
        float* dst = base + ((size_t)(bb * NHEADS + hh) * SEQ + s) * HDIM + dc;
        *(float4*)dst = make_float4(r[0], r[1], r[2], r[3]);
        *(float4*)(dst + 4) = make_float4(r[4], r[5], r[6], r[7]);
    }
}

// ---------------------------------------------------------------------------
// GEMM 2: output = ctx @ W_out + b_out
// ---------------------------------------------------------------------------
__global__ __launch_bounds__(256, 2) void gemm_out_kernel(
    const float* __restrict__ W, const float* __restrict__ bias,
    float* __restrict__ C)
{
    __shared__ float As[2][8][132];
    __shared__ float Bs[2][8][132];
    const int N = HIDDEN;
    int tid = threadIdx.x;
    int bm = blockIdx.y * 128, bn = blockIdx.x * 128;
    ull acc[8][4] = {};
    gemm_main(g_ctx, W, N, bm, bn, tid, As, Bs, acc);

    const int tx = tid & 15, ty = tid >> 4;
    int n0 = bn + tx * 8;
    float bb8[8];
    *(float4*)&bb8[0] = *(const float4*)&bias[n0];
    *(float4*)&bb8[4] = *(const float4*)&bias[n0 + 4];
#pragma unroll
    for (int i = 0; i < 8; i++) {
        int m = bm + ty * 8 + i;
        float r[8];
#pragma unroll
        for (int jp = 0; jp < 4; jp++) unpack2(acc[i][jp], r[2 * jp], r[2 * jp + 1]);
#pragma unroll
        for (int c = 0; c < 8; c++) r[c] += bb8[c];
        float* dst = C + (size_t)m * N + n0;
        *(float4*)dst = make_float4(r[0], r[1], r[2], r[3]);
        *(float4*)(dst + 4) = make_float4(r[4], r[5], r[6], r[7]);
    }
}

// ---------------------------------------------------------------------------
// Flash attention, 64-row Q tile per block, FFMA2, conflict-free key map.
// Thread (tx,ty): rows ty*4..+3 (as 2 packed pairs), keys tx+16j, out cols tx*4+j
// ---------------------------------------------------------------------------
#define APAD 68
#define ATTN_SMEM_FLOATS (3 * 64 * APAD + 64)

__global__ __launch_bounds__(256) void attn_kernel(
    const float* __restrict__ Q, const float* __restrict__ Kg,
    const float* __restrict__ Vg, const int* __restrict__ mask)
{
    extern __shared__ float sm[];
    float* QsT = sm;                  // [d=64][row=64] stride APAD (transposed Q)
    float* Ks  = QsT + 64 * APAD;     // [key=64][d=64] ; aliased as PsT [key][row]
    float* Vs  = Ks + 64 * APAD;      // [t=64][d=64]
    float* mbias = Vs + 64 * APAD;    // 64

    int tid = threadIdx.x;
    int qt = blockIdx.x, h = blockIdx.y, b = blockIdx.z;
    int bh = b * NHEADS + h;
    int qbase = qt * 64;
    const float* Qp = Q + ((size_t)bh * SEQ + qbase) * HDIM;
    const float* Kp = Kg + (size_t)bh * SEQ * HDIM;
    const float* Vp = Vg + (size_t)bh * SEQ * HDIM;

    // stage Q transposed (once) — full 64x64 tile = 1024 float4s
    for (int i = tid; i < 1024; i += 256) {
        float4 v = ((const float4*)Qp)[i];
        int r = i >> 4, c = (i & 15) << 2;
        QsT[(c + 0) * APAD + r] = v.x;
        QsT[(c + 1) * APAD + r] = v.y;
        QsT[(c + 2) * APAD + r] = v.z;
        QsT[(c + 3) * APAD + r] = v.w;
    }

    const int tx = tid & 15, ty = tid >> 4;
    ull o2[2][4] = {};                 // [row-pair][out col j]
    float mrow[4] = {-1e30f, -1e30f, -1e30f, -1e30f};
    float lrow[4] = {};
    const float scale = 0.125f;

    for (int kt = 0; kt <= qt; kt++) {
        __syncthreads();   // previous PV reads of PsT/Vs done
        {
            const float4* kg4 = (const float4*)(Kp + (size_t)(kt * 64) * HDIM);
            const float4* vg4 = (const float4*)(Vp + (size_t)(kt * 64) * HDIM);
            for (int i = tid; i < 1024; i += 256) {
                int r = i >> 4, c = (i & 15) << 2;
                *(float4*)&Ks[r * APAD + c] = kg4[i];
                *(float4*)&Vs[r * APAD + c] = vg4[i];
            }
            if (tid < 64)
                mbias[tid] = (mask[b * SEQ + kt * 64 + tid] == 0) ? -1e30f : 0.0f;
        }
        __syncthreads();

        // S = Q @ K^T : sv2[pair][j], keys tx+16j
        ull sv2[2][4] = {};
        for (int d0 = 0; d0 < 64; d0 += 4) {
            float kf[4][4];
#pragma unroll
            for (int j = 0; j < 4; j++)
                *(float4*)kf[j] = *(const float4*)&Ks[(tx + 16 * j) * APAD + d0];
#pragma unroll
            for (int dd = 0; dd < 4; dd++) {
                ulonglong2 q2 = *(const ulonglong2*)&QsT[(d0 + dd) * APAD + (ty << 2)];
#pragma unroll
                for (int j = 0; j < 4; j++) {
                    ull kd = dup2(kf[j][dd]);
                    fma2(sv2[0][j], q2.x, kd);
                    fma2(sv2[1][j], q2.y, kd);
                }
            }
        }
        float s[4][4];
#pragma unroll
        for (int ip = 0; ip < 2; ip++)
#pragma unroll
            for (int j = 0; j < 4; j++)
                unpack2(sv2[ip][j], s[2 * ip][j], s[2 * ip + 1][j]);

        // mask + scale
        float mb[4];
#pragma unroll
        for (int j = 0; j < 4; j++) mb[j] = mbias[tx + 16 * j];
        bool diag = (kt == qt);
#pragma unroll
        for (int i = 0; i < 4; i++) {
            int qpos = (ty << 2) + i;
#pragma unroll
            for (int j = 0; j < 4; j++) {
                int kpos = tx + 16 * j;
                float v = s[i][j] * scale + mb[j];
                if (diag && kpos > qpos) v = -1e30f;
                s[i][j] = v;
            }
        }

        // online softmax (rows live on 16 tx lanes)
        float fac[4];
#pragma unroll
        for (int i = 0; i < 4; i++) {
            float mx = fmaxf(fmaxf(s[i][0], s[i][1]), fmaxf(s[i][2], s[i][3]));
#pragma unroll
            for (int off = 8; off >= 1; off >>= 1)
                mx = fmaxf(mx, __shfl_xor_sync(0xffffffffu, mx, off, 16));
            float mnew = fmaxf(mrow[i], mx);
            fac[i] = __expf(mrow[i] - mnew);
            mrow[i] = mnew;
            float rs = 0.f;
#pragma unroll
            for (int j = 0; j < 4; j++) {
                float p = __expf(s[i][j] - mnew);
                s[i][j] = p;
                rs += p;
            }
#pragma unroll
            for (int off = 8; off >= 1; off >>= 1)
                rs += __shfl_xor_sync(0xffffffffu, rs, off, 16);
            lrow[i] = lrow[i] * fac[i] + rs;
        }
        ull facp0 = pack2(fac[0], fac[1]);
        ull facp1 = pack2(fac[2], fac[3]);
#pragma unroll
        for (int j = 0; j < 4; j++) {
            o2[0][j] = mul2(o2[0][j], facp0);
            o2[1][j] = mul2(o2[1][j], facp1);
        }

        // P -> PsT[key][row] (aliases Ks)
        __syncthreads();
        float* PsT = Ks;
#pragma unroll
        for (int j = 0; j < 4; j++)
#pragma unroll
            for (int i = 0; i < 4; i++)
                PsT[(tx + 16 * j) * APAD + (ty << 2) + i] = s[i][j];
        __syncthreads();

        // O += P @ V
#pragma unroll 4
        for (int t = 0; t < 64; t++) {
            ulonglong2 p2 = *(const ulonglong2*)&PsT[t * APAD + (ty << 2)];
            float4 v4 = *(const float4*)&Vs[t * APAD + (tx << 2)];
            ull vd;
            vd = dup2(v4.x); fma2(o2[0][0], p2.x, vd); fma2(o2[1][0], p2.y, vd);
            vd = dup2(v4.y); fma2(o2[0][1], p2.x, vd); fma2(o2[1][1], p2.y, vd);
            vd = dup2(v4.z); fma2(o2[0][2], p2.x, vd); fma2(o2[1][2], p2.y, vd);
            vd = dup2(v4.w); fma2(o2[0][3], p2.x, vd); fma2(o2[1][3], p2.y, vd);
        }
    }

    // normalize + write context
    float of[4][4];
#pragma unroll
    for (int ip = 0; ip < 2; ip++)
#pragma unroll
        for (int j = 0; j < 4; j++)
            unpack2(o2[ip][j], of[2 * ip][j], of[2 * ip + 1][j]);
#pragma unroll
    for (int i = 0; i < 4; i++) {
        float inv = 1.0f / lrow[i];
        int srow = qbase + (ty << 2) + i;
        float4 w = make_float4(of[i][0] * inv, of[i][1] * inv,
                               of[i][2] * inv, of[i][3] * inv);
        *(float4*)&g_ctx[(size_t)(b * SEQ + srow) * HIDDEN + h * HDIM + (tx << 2)] = w;
    }
}

// ---------------------------------------------------------------------------
extern "C" void kernel_launch(void* const* d_in, const int* in_sizes, int n_in,
                              void* d_out, int out_size) {
    const float* x    = (const float*)d_in[0];
    const int*   mask = (const int*)d_in[1];
    const float* Wqkv = (const float*)d_in[2];
    const float* bqkv = (const float*)d_in[3];
    const float* Wout = (const float*)d_in[4];
    const float* bout = (const float*)d_in[5];

    float* out = (float*)d_out;                     // [B,S,H]
    float* qo = out + (size_t)MTOT * HIDDEN;        // [B,h,S,d]
    float* ko = qo + (size_t)MTOT * HIDDEN;
    float* vo = ko + (size_t)MTOT * HIDDEN;

    const int attn_smem = ATTN_SMEM_FLOATS * (int)sizeof(float);
    cudaFuncSetAttribute(attn_kernel,
                         cudaFuncAttributeMaxDynamicSharedMemorySize, attn_smem);

    gemm_qkv_kernel<<<dim3(24, 32), 256>>>(x, Wqkv, bqkv, qo, ko, vo);
    attn_kernel<<<dim3(SEQ / 64, NHEADS, BATCH), 256, attn_smem>>>(qo, ko, vo, mask);
    gemm_out_kernel<<<dim3(8, 32), 256>>>(Wout, bout, out);
}